// round 8
// baseline (speedup 1.0000x reference)
#include <cuda_runtime.h>
#include <cuda_bf16.h>
#include <cstdint>

#define N_SPK 2048
#define M_UTT 8
#define D_EMB 512
#define N_ROWS (N_SPK * M_UTT)

#define MT 128                    // rows per CTA
#define NT 256                    // cols per pass
#define NPASS (N_SPK / NT)        // 8
#define KCH 64                    // k per B chunk
#define NKC (D_EMB / KCH)         // 8
#define TOTCH (NPASS * NKC)       // 64 chunks total
#define THREADS 512

// ---- dynamic shared memory layout ----
#define SM_A 0                              // 128 x 512 bf16 = 131072 B (8 chunks)
#define SM_B (MT * D_EMB * 2)               // 2 x (256 x 64 bf16 = 32768 B)
#define SM_RED (SM_B + 2 * NT * KCH * 2)    // 7 x 128 floats
#define SMEM_TOTAL (SM_RED + 3584 + 64)

// ---- device scratch (no allocation allowed) ----
__device__ float g_diag[N_ROWS];
__device__ __nv_bfloat16 g_ebf[(size_t)N_ROWS * D_EMB];
__device__ __nv_bfloat16 g_cbf[(size_t)N_SPK * D_EMB];

// ---------------------------------------------------------------- helpers
__device__ __forceinline__ uint32_t smem_u32(const void* p) {
    uint32_t a;
    asm("{ .reg .u64 t; cvta.to.shared.u64 t, %1; cvt.u32.u64 %0, t; }"
        : "=r"(a) : "l"(p));
    return a;
}
__device__ __forceinline__ uint32_t sw128(uint32_t off) {
    return off ^ ((off >> 3) & 0x70);
}
__device__ __forceinline__ void ldsm_x4(uint32_t* r, uint32_t a) {
    asm volatile("ldmatrix.sync.aligned.m8n8.x4.shared.b16 {%0,%1,%2,%3}, [%4];"
                 : "=r"(r[0]), "=r"(r[1]), "=r"(r[2]), "=r"(r[3]) : "r"(a));
}
__device__ __forceinline__ void ldsm_x4t(uint32_t* r, uint32_t a) {
    asm volatile("ldmatrix.sync.aligned.m8n8.x4.trans.shared.b16 {%0,%1,%2,%3}, [%4];"
                 : "=r"(r[0]), "=r"(r[1]), "=r"(r[2]), "=r"(r[3]) : "r"(a));
}
__device__ __forceinline__ void mma16816(float* c, const uint32_t* a,
                                         uint32_t b0, uint32_t b1) {
    asm volatile(
        "mma.sync.aligned.m16n8k16.row.col.f32.bf16.bf16.f32 "
        "{%0,%1,%2,%3}, {%4,%5,%6,%7}, {%8,%9}, {%0,%1,%2,%3};"
        : "+f"(c[0]), "+f"(c[1]), "+f"(c[2]), "+f"(c[3])
        : "r"(a[0]), "r"(a[1]), "r"(a[2]), "r"(a[3]), "r"(b0), "r"(b1));
}
#define CPASYNC16(dst, src)                                                   \
    asm volatile("cp.async.ca.shared.global [%0], [%1], 16;" ::"r"(dst),      \
                 "l"(src) : "memory")
#define CPCOMMIT() asm volatile("cp.async.commit_group;" ::: "memory")
#define CPWAIT0() asm volatile("cp.async.wait_group 0;" ::: "memory")

// ---------------------------------------------------------------------------
// Kernel A: per-speaker prep: centroids, LOO diag values, bf16 conversions.
// ---------------------------------------------------------------------------
__global__ __launch_bounds__(64) void prep_kernel(const float* __restrict__ e,
                                                  float* __restrict__ out) {
    int n = blockIdx.x;
    int t = threadIdx.x;  // 64 threads x 8 floats
    const float* base = e + (size_t)n * (M_UTT * D_EMB) + t * 8;

    float4 r0[M_UTT], r1[M_UTT];
    float s[8];
#pragma unroll
    for (int j = 0; j < 8; ++j) s[j] = 0.f;
#pragma unroll
    for (int m = 0; m < M_UTT; ++m) {
        r0[m] = *(const float4*)(base + m * D_EMB);
        r1[m] = *(const float4*)(base + m * D_EMB + 4);
        s[0] += r0[m].x; s[1] += r0[m].y; s[2] += r0[m].z; s[3] += r0[m].w;
        s[4] += r1[m].x; s[5] += r1[m].y; s[6] += r1[m].z; s[7] += r1[m].w;
    }

#pragma unroll
    for (int m = 0; m < M_UTT; ++m) {
        __nv_bfloat162 p0 = __floats2bfloat162_rn(r0[m].x, r0[m].y);
        __nv_bfloat162 p1 = __floats2bfloat162_rn(r0[m].z, r0[m].w);
        __nv_bfloat162 p2 = __floats2bfloat162_rn(r1[m].x, r1[m].y);
        __nv_bfloat162 p3 = __floats2bfloat162_rn(r1[m].z, r1[m].w);
        uint4 v = make_uint4(*(uint32_t*)&p0, *(uint32_t*)&p1,
                             *(uint32_t*)&p2, *(uint32_t*)&p3);
        *(uint4*)&g_ebf[((size_t)n * M_UTT + m) * D_EMB + t * 8] = v;
    }

    float p[9];
    p[8] = s[0]*s[0]+s[1]*s[1]+s[2]*s[2]+s[3]*s[3]
         + s[4]*s[4]+s[5]*s[5]+s[6]*s[6]+s[7]*s[7];
#pragma unroll
    for (int m = 0; m < M_UTT; ++m) {
        p[m] = r0[m].x*s[0]+r0[m].y*s[1]+r0[m].z*s[2]+r0[m].w*s[3]
             + r1[m].x*s[4]+r1[m].y*s[5]+r1[m].z*s[6]+r1[m].w*s[7];
    }

    __shared__ float red[2][9];
    int wid = t >> 5, lane = t & 31;
#pragma unroll
    for (int i = 0; i < 9; ++i) {
        float v = p[i];
#pragma unroll
        for (int off = 16; off > 0; off >>= 1)
            v += __shfl_xor_sync(0xffffffffu, v, off);
        if (lane == 0) red[wid][i] = v;
    }
    __syncthreads();

    float S2 = red[0][8] + red[1][8];
    float inv = rsqrtf(S2);
    {
        __nv_bfloat162 p0 = __floats2bfloat162_rn(s[0]*inv, s[1]*inv);
        __nv_bfloat162 p1 = __floats2bfloat162_rn(s[2]*inv, s[3]*inv);
        __nv_bfloat162 p2 = __floats2bfloat162_rn(s[4]*inv, s[5]*inv);
        __nv_bfloat162 p3 = __floats2bfloat162_rn(s[6]*inv, s[7]*inv);
        uint4 v = make_uint4(*(uint32_t*)&p0, *(uint32_t*)&p1,
                             *(uint32_t*)&p2, *(uint32_t*)&p3);
        *(uint4*)&g_cbf[(size_t)n * D_EMB + t * 8] = v;
    }

    if (t < M_UTT) {
        float tm = red[0][t] + red[1][t];
        g_diag[n * M_UTT + t] =
            (tm - 1.f) * rsqrtf(fmaxf(S2 - 2.f * tm + 1.f, 1e-20f));
    }
    if (n == 0 && t == 0) out[0] = 0.f;
}

// ---------------------------------------------------------------------------
// Kernel B: mma.sync bf16 GEMM (128 x 2048 x 512 per CTA) fused with
// softmax-sum + cross-entropy. 512 threads, 16 warps in a 2M x 8N grid,
// warp tile 64x32; NT=256-col passes, double-buffered 32KB B chunks.
// Logits bounded by |w|+|b|: plain exp-sum, no running max needed.
// ---------------------------------------------------------------------------
__global__ __launch_bounds__(THREADS, 1)
void loss_kernel(const float* __restrict__ wp, const float* __restrict__ bp,
                 float* __restrict__ out) {
    extern __shared__ char smem[];
    const uint32_t sb = smem_u32(smem);
    const int tid = threadIdx.x;
    const int wid = tid >> 5, l = tid & 31;
    const int wm = wid >> 3, wn = wid & 7;   // 2 x 8 warp grid
    const int row0 = blockIdx.x * MT;

    // B chunk cp.async: chunk g covers cols [(g>>3)*256,+256), k [(g&7)*64,+64)
    auto issueB = [&](int g) {
        if (g < TOTCH) {
            const char* src = (const char*)g_cbf + (size_t)(g >> 3) * (NT * 1024) +
                              (g & 7) * 128;
            uint32_t dst = sb + SM_B + (g & 1) * 32768;
            for (int i = tid; i < 2048; i += THREADS) {
                int r = i >> 3, b = (i & 7) << 4;
                CPASYNC16(dst + sw128(r * 128 + b),
                          (const void*)(src + (size_t)r * 1024 + b));
            }
            CPCOMMIT();
        }
    };
    issueB(0);

    // ---- A tile: 128 rows x 512 bf16, 8 k-chunks of 128B, SW128 swizzled
    {
        const char* src = (const char*)g_ebf + (size_t)row0 * 1024;
        for (int i = tid; i < 8192; i += THREADS) {
            int r = i >> 6;
            int bc = (i & 63) << 4;
            uint4 v = *(const uint4*)(src + (size_t)r * 1024 + bc);
            int c = bc >> 7, b = bc & 127;
            *(uint4*)(smem + SM_A + c * 16384 + sw128(r * 128 + b)) = v;
        }
    }

    const float wa = fabsf(*wp), bb = *bp;

    // 8 rows owned by this thread: q = rb*2+h -> wm*64 + rb*16 + h*8 + (l>>2)
    float dval[8];
#pragma unroll
    for (int q = 0; q < 8; ++q) {
        int rl = wm * 64 + (q >> 1) * 16 + (q & 1) * 8 + (l >> 2);
        dval[q] = fmaf(wa, g_diag[row0 + rl], bb);
    }

    // lane-invariant ldmatrix address components
    const uint32_t rA = (uint32_t)(wm * 64 + (l & 15)) * 128 + ((l >> 4) << 4);
    const uint32_t nB = (uint32_t)(((l >> 4) << 3) + (l & 7)) * 128 +
                        (((l >> 3) & 1) << 4) + (uint32_t)wn * 4096;

    float s[8];
#pragma unroll
    for (int q = 0; q < 8; ++q) s[q] = 0.f;

    for (int pass = 0; pass < NPASS; ++pass) {
        float acc[4][4][4];
#pragma unroll
        for (int rb = 0; rb < 4; ++rb)
#pragma unroll
            for (int f = 0; f < 4; ++f)
                acc[rb][f][0] = acc[rb][f][1] = acc[rb][f][2] = acc[rb][f][3] = 0.f;

        for (int kc = 0; kc < NKC; ++kc) {
            const int g = pass * NKC + kc;
            CPWAIT0();                 // chunk g resident (this thread's part)
            __syncthreads();           // everyone's copies visible; old buf free
            issueB(g + 1);             // prefetch next chunk into other buffer

            const uint32_t abase = sb + SM_A + kc * 16384;
            const uint32_t bbase = sb + SM_B + (g & 1) * 32768;
#pragma unroll
            for (int ks = 0; ks < 4; ++ks) {
                uint32_t a[4][4];
#pragma unroll
                for (int rb = 0; rb < 4; ++rb)
                    ldsm_x4(a[rb], abase + sw128(rA + rb * 2048 + ks * 32));
#pragma unroll
                for (int f2 = 0; f2 < 2; ++f2) {
                    uint32_t b[4];
                    ldsm_x4t(b, bbase + sw128(nB + f2 * 2048 + ks * 32));
#pragma unroll
                    for (int rb = 0; rb < 4; ++rb) {
                        mma16816(acc[rb][2 * f2],     a[rb], b[0], b[1]);
                        mma16816(acc[rb][2 * f2 + 1], a[rb], b[2], b[3]);
                    }
                }
            }
        }

        // ---- epilogue: scale + diag replace + exp-sum over this warp's 32 cols
        const int n0 = pass * NT + wn * 32;
#pragma unroll
        for (int rb = 0; rb < 4; ++rb) {
            const int spk0 = (row0 + wm * 64 + rb * 16 + (l >> 2)) >> 3;
            const int spk1 = (row0 + wm * 64 + rb * 16 + 8 + (l >> 2)) >> 3;
#pragma unroll
            for (int f = 0; f < 4; ++f) {
                const int c = n0 + f * 8 + (l & 3) * 2;
                float x00 = fmaf(wa, acc[rb][f][0], bb);
                float x01 = fmaf(wa, acc[rb][f][1], bb);
                float x10 = fmaf(wa, acc[rb][f][2], bb);
                float x11 = fmaf(wa, acc[rb][f][3], bb);
                if (c     == spk0) x00 = dval[rb * 2];
                if (c + 1 == spk0) x01 = dval[rb * 2];
                if (c     == spk1) x10 = dval[rb * 2 + 1];
                if (c + 1 == spk1) x11 = dval[rb * 2 + 1];
                s[rb * 2]     += __expf(x00) + __expf(x01);
                s[rb * 2 + 1] += __expf(x10) + __expf(x11);
            }
        }
    }

    // ---- reduce the 4 lanes (quad) sharing each row
#pragma unroll
    for (int q = 0; q < 8; ++q) {
        s[q] += __shfl_xor_sync(0xffffffffu, s[q], 1);
        s[q] += __shfl_xor_sync(0xffffffffu, s[q], 2);
    }

    // ---- combine the 8 column warps (wn=0..7) per row via smem
    float* red = (float*)(smem + SM_RED);
    __syncthreads();
    if (wn > 0 && (l & 3) == 0) {
#pragma unroll
        for (int q = 0; q < 8; ++q) {
            int rl = wm * 64 + (q >> 1) * 16 + (q & 1) * 8 + (l >> 2);
            red[(wn - 1) * 128 + rl] = s[q];
        }
    }
    __syncthreads();
    float part = 0.f;
    if (wn == 0 && (l & 3) == 0) {
#pragma unroll
        for (int q = 0; q < 8; ++q) {
            int rl = wm * 64 + (q >> 1) * 16 + (q & 1) * 8 + (l >> 2);
            float tot = s[q];
#pragma unroll
            for (int v = 0; v < 7; ++v) tot += red[v * 128 + rl];
            part += __logf(tot) - dval[q];
        }
    }
    part += __shfl_xor_sync(0xffffffffu, part, 4);
    part += __shfl_xor_sync(0xffffffffu, part, 8);
    part += __shfl_xor_sync(0xffffffffu, part, 16);
    if (wn == 0 && l == 0) atomicAdd(out, part * (1.0f / N_ROWS));
}

// ---------------------------------------------------------------------------
extern "C" void kernel_launch(void* const* d_in, const int* in_sizes, int n_in,
                              void* d_out, int out_size) {
    const float* e = (const float*)d_in[0];   // embeds [16384,512] f32
    const float* w = (const float*)d_in[1];   // scalar
    const float* b = (const float*)d_in[2];   // scalar
    float* out = (float*)d_out;

    cudaFuncSetAttribute(loss_kernel, cudaFuncAttributeMaxDynamicSharedMemorySize,
                         SMEM_TOTAL);
    prep_kernel<<<N_SPK, 64>>>(e, out);
    loss_kernel<<<N_ROWS / MT, THREADS, SMEM_TOTAL>>>(w, b, out);
}

// round 9
// speedup vs baseline: 1.1060x; 1.1060x over previous
#include <cuda_runtime.h>
#include <cuda_bf16.h>
#include <cstdint>

#define N_SPK 2048
#define M_UTT 8
#define D_EMB 512
#define N_ROWS (N_SPK * M_UTT)

#define MT 128                    // rows per CTA
#define NTOT 1024                 // cols per CTA (half of N_SPK)
#define NT 128                    // cols per pass
#define NPASS (NTOT / NT)         // 8
#define KCH 64                    // k per chunk
#define NKC (D_EMB / KCH)         // 8
#define TOTCH (NPASS * NKC)       // 64 chunks per CTA
#define THREADS 256

// ---- dynamic shared memory layout: 2 buffers of (A 16KB + B 16KB) ----
#define SM_BUF 0
#define BUFSZ  32768              // 16KB A + 16KB B
#define SM_RED (2 * BUFSZ)        // 3 x 128 floats
#define SMEM_TOTAL (SM_RED + 1536 + 64)

// ---- device scratch (no allocation allowed) ----
__device__ float g_diag[N_ROWS];
__device__ float g_rowsum[N_ROWS];
__device__ __nv_bfloat16 g_ebf[(size_t)N_ROWS * D_EMB];
__device__ __nv_bfloat16 g_cbf[(size_t)N_SPK * D_EMB];

// ---------------------------------------------------------------- helpers
__device__ __forceinline__ uint32_t smem_u32(const void* p) {
    uint32_t a;
    asm("{ .reg .u64 t; cvta.to.shared.u64 t, %1; cvt.u32.u64 %0, t; }"
        : "=r"(a) : "l"(p));
    return a;
}
__device__ __forceinline__ uint32_t sw128(uint32_t off) {
    return off ^ ((off >> 3) & 0x70);
}
__device__ __forceinline__ void ldsm_x4(uint32_t* r, uint32_t a) {
    asm volatile("ldmatrix.sync.aligned.m8n8.x4.shared.b16 {%0,%1,%2,%3}, [%4];"
                 : "=r"(r[0]), "=r"(r[1]), "=r"(r[2]), "=r"(r[3]) : "r"(a));
}
__device__ __forceinline__ void ldsm_x4t(uint32_t* r, uint32_t a) {
    asm volatile("ldmatrix.sync.aligned.m8n8.x4.trans.shared.b16 {%0,%1,%2,%3}, [%4];"
                 : "=r"(r[0]), "=r"(r[1]), "=r"(r[2]), "=r"(r[3]) : "r"(a));
}
__device__ __forceinline__ void mma16816(float* c, const uint32_t* a,
                                         uint32_t b0, uint32_t b1) {
    asm volatile(
        "mma.sync.aligned.m16n8k16.row.col.f32.bf16.bf16.f32 "
        "{%0,%1,%2,%3}, {%4,%5,%6,%7}, {%8,%9}, {%0,%1,%2,%3};"
        : "+f"(c[0]), "+f"(c[1]), "+f"(c[2]), "+f"(c[3])
        : "r"(a[0]), "r"(a[1]), "r"(a[2]), "r"(a[3]), "r"(b0), "r"(b1));
}
#define CPASYNC16(dst, src)                                                   \
    asm volatile("cp.async.ca.shared.global [%0], [%1], 16;" ::"r"(dst),      \
                 "l"(src) : "memory")
#define CPCOMMIT() asm volatile("cp.async.commit_group;" ::: "memory")
#define CPWAIT0() asm volatile("cp.async.wait_group 0;" ::: "memory")

// ---------------------------------------------------------------------------
// Kernel A: per-speaker prep: centroids, LOO diag values, bf16 conversions,
// zero g_rowsum and the output accumulator.
// ---------------------------------------------------------------------------
__global__ __launch_bounds__(64) void prep_kernel(const float* __restrict__ e,
                                                  float* __restrict__ out) {
    int n = blockIdx.x;
    int t = threadIdx.x;  // 64 threads x 8 floats
    const float* base = e + (size_t)n * (M_UTT * D_EMB) + t * 8;

    if (n < N_ROWS / 64) g_rowsum[n * 64 + t] = 0.f;

    float4 r0[M_UTT], r1[M_UTT];
    float s[8];
#pragma unroll
    for (int j = 0; j < 8; ++j) s[j] = 0.f;
#pragma unroll
    for (int m = 0; m < M_UTT; ++m) {
        r0[m] = *(const float4*)(base + m * D_EMB);
        r1[m] = *(const float4*)(base + m * D_EMB + 4);
        s[0] += r0[m].x; s[1] += r0[m].y; s[2] += r0[m].z; s[3] += r0[m].w;
        s[4] += r1[m].x; s[5] += r1[m].y; s[6] += r1[m].z; s[7] += r1[m].w;
    }

#pragma unroll
    for (int m = 0; m < M_UTT; ++m) {
        __nv_bfloat162 p0 = __floats2bfloat162_rn(r0[m].x, r0[m].y);
        __nv_bfloat162 p1 = __floats2bfloat162_rn(r0[m].z, r0[m].w);
        __nv_bfloat162 p2 = __floats2bfloat162_rn(r1[m].x, r1[m].y);
        __nv_bfloat162 p3 = __floats2bfloat162_rn(r1[m].z, r1[m].w);
        uint4 v = make_uint4(*(uint32_t*)&p0, *(uint32_t*)&p1,
                             *(uint32_t*)&p2, *(uint32_t*)&p3);
        *(uint4*)&g_ebf[((size_t)n * M_UTT + m) * D_EMB + t * 8] = v;
    }

    float p[9];
    p[8] = s[0]*s[0]+s[1]*s[1]+s[2]*s[2]+s[3]*s[3]
         + s[4]*s[4]+s[5]*s[5]+s[6]*s[6]+s[7]*s[7];
#pragma unroll
    for (int m = 0; m < M_UTT; ++m) {
        p[m] = r0[m].x*s[0]+r0[m].y*s[1]+r0[m].z*s[2]+r0[m].w*s[3]
             + r1[m].x*s[4]+r1[m].y*s[5]+r1[m].z*s[6]+r1[m].w*s[7];
    }

    __shared__ float red[2][9];
    int wid = t >> 5, lane = t & 31;
#pragma unroll
    for (int i = 0; i < 9; ++i) {
        float v = p[i];
#pragma unroll
        for (int off = 16; off > 0; off >>= 1)
            v += __shfl_xor_sync(0xffffffffu, v, off);
        if (lane == 0) red[wid][i] = v;
    }
    __syncthreads();

    float S2 = red[0][8] + red[1][8];
    float inv = rsqrtf(S2);
    {
        __nv_bfloat162 p0 = __floats2bfloat162_rn(s[0]*inv, s[1]*inv);
        __nv_bfloat162 p1 = __floats2bfloat162_rn(s[2]*inv, s[3]*inv);
        __nv_bfloat162 p2 = __floats2bfloat162_rn(s[4]*inv, s[5]*inv);
        __nv_bfloat162 p3 = __floats2bfloat162_rn(s[6]*inv, s[7]*inv);
        uint4 v = make_uint4(*(uint32_t*)&p0, *(uint32_t*)&p1,
                             *(uint32_t*)&p2, *(uint32_t*)&p3);
        *(uint4*)&g_cbf[(size_t)n * D_EMB + t * 8] = v;
    }

    if (t < M_UTT) {
        float tm = red[0][t] + red[1][t];
        g_diag[n * M_UTT + t] =
            (tm - 1.f) * rsqrtf(fmaxf(S2 - 2.f * tm + 1.f, 1e-20f));
    }
    if (n == 0 && t == 0) out[0] = 0.f;
}

// ---------------------------------------------------------------------------
// Kernel B: mma.sync bf16 GEMM fused with exp-sum. Each CTA: 128 rows x
// 1024 cols (half the speakers). 256 CTAs -> 2 CTAs/SM so chunk-boundary
// stalls of one CTA overlap the other's mainloop. Both A and B streamed in
// 16KB k-chunks (double-buffered). Partial row exp-sums -> atomicAdd to
// g_rowsum. Logits bounded by |w|+|b|: no running max needed.
// ---------------------------------------------------------------------------
__global__ __launch_bounds__(THREADS, 2)
void loss_kernel(const float* __restrict__ wp, const float* __restrict__ bp) {
    extern __shared__ char smem[];
    const uint32_t sb = smem_u32(smem);
    const int tid = threadIdx.x;
    const int wid = tid >> 5, l = tid & 31;
    const int wm = wid >> 2, wn = wid & 3;       // 2M x 4N warp grid
    const int row0 = (blockIdx.x >> 1) * MT;
    const int col0 = (blockIdx.x & 1) * NTOT;

    const float wa = fabsf(*wp), bb = *bp;

    // chunk g: pass p=g>>3 covers cols [col0+p*128,+128), kc=g&7 covers
    // k [kc*64,+64). Each buffer: A rows then B rows, 128 rows x 128B each.
    auto issueChunk = [&](int g) {
        if (g < TOTCH) {
            const uint32_t dst = sb + SM_BUF + (g & 1) * BUFSZ;
            const char* srcA = (const char*)g_ebf + (size_t)row0 * 1024 +
                               (g & 7) * 128;
            const char* srcB = (const char*)g_cbf +
                               (size_t)(col0 + (g >> 3) * NT) * 1024 +
                               (g & 7) * 128;
#pragma unroll
            for (int i = tid; i < 1024; i += THREADS) {
                int r = i >> 3, b = (i & 7) << 4;
                uint32_t sw = sw128(r * 128 + b);
                CPASYNC16(dst + sw, (const void*)(srcA + (size_t)r * 1024 + b));
                CPASYNC16(dst + 16384 + sw,
                          (const void*)(srcB + (size_t)r * 1024 + b));
            }
            CPCOMMIT();
        }
    };
    issueChunk(0);

    // per-thread rows: q -> wm*64 + (q>>1)*16 + (q&1)*8 + (l>>2)
    float dval[8];
#pragma unroll
    for (int q = 0; q < 8; ++q) {
        int rl = wm * 64 + (q >> 1) * 16 + (q & 1) * 8 + (l >> 2);
        dval[q] = fmaf(wa, g_diag[row0 + rl], bb);
    }

    // lane-invariant ldmatrix address components
    const uint32_t rA = (uint32_t)(wm * 64 + (l & 15)) * 128 + ((l >> 4) << 4);
    const uint32_t nB = (uint32_t)(((l >> 4) << 3) + (l & 7)) * 128 +
                        (((l >> 3) & 1) << 4) + (uint32_t)wn * 4096;

    float s[8];
#pragma unroll
    for (int q = 0; q < 8; ++q) s[q] = 0.f;

    for (int pass = 0; pass < NPASS; ++pass) {
        float acc[4][4][4];
#pragma unroll
        for (int rb = 0; rb < 4; ++rb)
#pragma unroll
            for (int f = 0; f < 4; ++f)
                acc[rb][f][0] = acc[rb][f][1] = acc[rb][f][2] = acc[rb][f][3] = 0.f;

        for (int kc = 0; kc < NKC; ++kc) {
            const int g = pass * NKC + kc;
            CPWAIT0();                 // chunk g resident (this thread's part)
            __syncthreads();           // visible to all; previous buffer free
            issueChunk(g + 1);         // prefetch next chunk into other buffer

            const uint32_t abase = sb + SM_BUF + (g & 1) * BUFSZ;
            const uint32_t bbase = abase + 16384;
#pragma unroll
            for (int ks = 0; ks < 4; ++ks) {
                uint32_t a[4][4];
#pragma unroll
                for (int rb = 0; rb < 4; ++rb)
                    ldsm_x4(a[rb], abase + sw128(rA + rb * 2048 + ks * 32));
#pragma unroll
                for (int f2 = 0; f2 < 2; ++f2) {
                    uint32_t b[4];
                    ldsm_x4t(b, bbase + sw128(nB + f2 * 2048 + ks * 32));
#pragma unroll
                    for (int rb = 0; rb < 4; ++rb) {
                        mma16816(acc[rb][2 * f2],     a[rb], b[0], b[1]);
                        mma16816(acc[rb][2 * f2 + 1], a[rb], b[2], b[3]);
                    }
                }
            }
        }

        // ---- epilogue: scale + diag replace + exp-sum over this warp's 32 cols
        const int n0 = col0 + pass * NT + wn * 32;
#pragma unroll
        for (int rb = 0; rb < 4; ++rb) {
            const int spk0 = (row0 + wm * 64 + rb * 16 + (l >> 2)) >> 3;
            const int spk1 = (row0 + wm * 64 + rb * 16 + 8 + (l >> 2)) >> 3;
#pragma unroll
            for (int f = 0; f < 4; ++f) {
                const int c = n0 + f * 8 + (l & 3) * 2;
                float x00 = fmaf(wa, acc[rb][f][0], bb);
                float x01 = fmaf(wa, acc[rb][f][1], bb);
                float x10 = fmaf(wa, acc[rb][f][2], bb);
                float x11 = fmaf(wa, acc[rb][f][3], bb);
                if (c     == spk0) x00 = dval[rb * 2];
                if (c + 1 == spk0) x01 = dval[rb * 2];
                if (c     == spk1) x10 = dval[rb * 2 + 1];
                if (c + 1 == spk1) x11 = dval[rb * 2 + 1];
                s[rb * 2]     += __expf(x00) + __expf(x01);
                s[rb * 2 + 1] += __expf(x10) + __expf(x11);
            }
        }
    }

    // ---- reduce the 4 lanes (quad) sharing each row
#pragma unroll
    for (int q = 0; q < 8; ++q) {
        s[q] += __shfl_xor_sync(0xffffffffu, s[q], 1);
        s[q] += __shfl_xor_sync(0xffffffffu, s[q], 2);
    }

    // ---- combine the 4 column warps per row via smem, then atomic to global
    float* red = (float*)(smem + SM_RED);
    __syncthreads();
    if (wn > 0 && (l & 3) == 0) {
#pragma unroll
        for (int q = 0; q < 8; ++q) {
            int rl = wm * 64 + (q >> 1) * 16 + (q & 1) * 8 + (l >> 2);
            red[(wn - 1) * 128 + rl] = s[q];
        }
    }
    __syncthreads();
    if (wn == 0 && (l & 3) == 0) {
#pragma unroll
        for (int q = 0; q < 8; ++q) {
            int rl = wm * 64 + (q >> 1) * 16 + (q & 1) * 8 + (l >> 2);
            float tot = s[q] + red[rl] + red[128 + rl] + red[256 + rl];
            atomicAdd(&g_rowsum[row0 + rl], tot);
        }
    }
}

// ---------------------------------------------------------------------------
// Kernel C: finish — loss = mean over rows of log(rowsum) - dval.
// ---------------------------------------------------------------------------
__global__ __launch_bounds__(512) void finish_kernel(const float* __restrict__ wp,
                                                     const float* __restrict__ bp,
                                                     float* __restrict__ out) {
    const float wa = fabsf(*wp), bb = *bp;
    int i = blockIdx.x * 512 + threadIdx.x;
    float lr = __logf(g_rowsum[i]) - fmaf(wa, g_diag[i], bb);
#pragma unroll
    for (int off = 16; off > 0; off >>= 1)
        lr += __shfl_xor_sync(0xffffffffu, lr, off);
    __shared__ float part[16];
    if ((threadIdx.x & 31) == 0) part[threadIdx.x >> 5] = lr;
    __syncthreads();
    if (threadIdx.x == 0) {
        float t = 0.f;
#pragma unroll
        for (int k = 0; k < 16; ++k) t += part[k];
        atomicAdd(out, t * (1.0f / N_ROWS));
    }
}

// ---------------------------------------------------------------------------
extern "C" void kernel_launch(void* const* d_in, const int* in_sizes, int n_in,
                              void* d_out, int out_size) {
    const float* e = (const float*)d_in[0];   // embeds [16384,512] f32
    const float* w = (const float*)d_in[1];   // scalar
    const float* b = (const float*)d_in[2];   // scalar
    float* out = (float*)d_out;

    cudaFuncSetAttribute(loss_kernel, cudaFuncAttributeMaxDynamicSharedMemorySize,
                         SMEM_TOTAL);
    prep_kernel<<<N_SPK, 64>>>(e, out);
    loss_kernel<<<(N_ROWS / MT) * 2, THREADS, SMEM_TOTAL>>>(w, b);
    finish_kernel<<<N_ROWS / 512, 512>>>(w, b, out);
}